// round 5
// baseline (speedup 1.0000x reference)
#include <cuda_runtime.h>
#include <math.h>
#include <stdint.h>

#define IMG_SIZE 255.0f
#define MAXB 64
#define MAXA 65536
#define CAP   32768
#define CHUNK 4096

// ---------------- device scratch (zero-initialized at module load; the final
// block of k_pass2 re-zeroes everything so each graph replay starts clean) ----
__device__ int      g_hist [MAXB][256];   // per-row byte-3 histogram of keys
__device__ int      g_hist2[MAXB][256];   // byte-2 histogram within boundary bin
__device__ int      g_rowpos[MAXB];
__device__ unsigned g_cand[MAXB][CAP];    // boundary-bin candidate keys
__device__ int      g_ncand[MAXB];
__device__ int      g_rowticket[MAXB];    // pass2 blocks finished per row
__device__ int      g_rowdone;            // rows fully refined
// floats: 0 loss_loc_sum, 1 pos_nll_sum, 2 pos_err_sum, 3 size_x, 4 size_y, 5 neg_nll_sel
__device__ float    g_f[8];
// ints:   0 N, 1 pos_correct, 2 neg_selected_total, 3 neg_correct
__device__ int      g_i[4];

__device__ __forceinline__ float smooth_l1(float x) {
    float ax = fabsf(x);
    return (ax < 1.0f) ? 0.5f * x * x : ax - 0.5f;
}
__device__ __forceinline__ float softplus(float d) {     // nll at target 0
    return fmaxf(d, 0.0f) + log1pf(expf(-fabsf(d)));
}
__device__ __forceinline__ unsigned f2ord(float f) {
    unsigned u = __float_as_uint(f);
    return (u & 0x80000000u) ? ~u : (u | 0x80000000u);
}
__device__ __forceinline__ float ord2f(unsigned k) {
    unsigned u = (k & 0x80000000u) ? (k & 0x7FFFFFFFu) : ~k;
    return __uint_as_float(u);
}

// Parallel cutoff over a 256-bin histogram in shared s[256] (destroyed).
// Returns c, kk with: sum(bins>c) < k <= sum(bins>=c), kk = k - sum(bins>c).
// blockDim.x == 256; caller must __syncthreads() after filling s.
__device__ __forceinline__ void suffix_cutoff(int* s, int k, int* out_c, int* out_kk) {
    int t = threadIdx.x;
    #pragma unroll
    for (int off = 1; off < 256; off <<= 1) {
        int add = (t + off < 256) ? s[t + off] : 0;
        __syncthreads();
        s[t] += add;
        __syncthreads();
    }
    __shared__ int sc, skk;
    if (t == 0) { sc = 0; skk = k; }
    __syncthreads();
    int St = s[t];
    int Sn = (t < 255) ? s[t + 1] : 0;
    if (Sn < k && k <= St) { sc = t; skk = k - Sn; }
    __syncthreads();
    *out_c = sc; *out_kk = skk;
}

__device__ __forceinline__ int row_k(int b, int A) {
    int k = 3 * g_rowpos[b];
    if (k < 10) k = 10;
    if (k > A - 1) k = A - 1;
    return k;
}

// orderable key (0 unless label==0) and pos flag
__device__ __forceinline__ unsigned make_key(float4 g, float areaA, float4 pr,
                                             float d, bool* pos) {
    float ax0 = pr.x - pr.z * 0.5f, ay0 = pr.y - pr.w * 0.5f;
    float ax1 = pr.x + pr.z * 0.5f, ay1 = pr.y + pr.w * 0.5f;
    float iw = fmaxf(fminf(g.z, ax1) - fmaxf(g.x, ax0), 0.0f);
    float ih = fmaxf(fminf(g.w, ay1) - fmaxf(g.y, ay0), 0.0f);
    float inter = iw * ih;
    float iou = inter / (areaA + (ax1 - ax0) * (ay1 - ay0) - inter);
    *pos = (iou >= 0.6f);
    return (iou <= 0.3f) ? f2ord(d) : 0u;
}

// ---------------- K1: histogram + sparse positive work ----------------
__global__ void __launch_bounds__(256) k_pass1(
        const float*  __restrict__ loc,
        const float2* __restrict__ conf,
        const float4* __restrict__ gt4,
        const float4* __restrict__ anch,
        int A) {
    int b = blockIdx.y;
    int base = blockIdx.x * CHUNK;
    __shared__ int sh[256];
    sh[threadIdx.x] = 0;
    __syncthreads();

    float4 g = gt4[b];
    float areaA = (g.z - g.x) * (g.w - g.y);
    size_t rowoff = (size_t)b * A;

    #pragma unroll 4
    for (int it = 0; it < CHUNK / 256; ++it) {
        int a = base + it * 256 + threadIdx.x;   // A % CHUNK == 0
        float4 pr = anch[a];
        float2 c = conf[rowoff + a];
        float d = c.y - c.x;
        bool pos;
        unsigned key = make_key(g, areaA, pr, d, &pos);

        unsigned bin = key >> 24;
        unsigned mask = __match_any_sync(0xffffffffu, bin);
        if ((threadIdx.x & 31) == (unsigned)(__ffs(mask) - 1))
            atomicAdd(&sh[bin], __popc(mask));

        if (pos) {
            atomicAdd(&g_rowpos[b], 1);
            atomicAdd(&g_i[0], 1);
            atomicAdd(&g_f[1], softplus(-d));          // nll at target 1
            if (d > 0.0f) atomicAdd(&g_i[1], 1);
            const float* lp = loc + (rowoff + a) * 4;
            float l0 = lp[0], l1 = lp[1], l2 = lp[2], l3 = lp[3];
            float gw = g.z - g.x, gh = g.w - g.y;
            float gcx = (g.x + g.z) * 0.5f, gcy = (g.y + g.w) * 0.5f;
            float e0 = (gcx - pr.x) / (0.1f * pr.z);
            float e1 = (gcy - pr.y) / (0.1f * pr.w);
            float e2 = logf(gw / pr.z) / 0.2f;
            float e3 = logf(gh / pr.w) / 0.2f;
            atomicAdd(&g_f[0], smooth_l1(l0 - e0) + smooth_l1(l1 - e1) +
                               smooth_l1(l2 - e2) + smooth_l1(l3 - e3));
            float dcx = pr.x + l0 * 0.1f * pr.z;
            float dcy = pr.y + l1 * 0.1f * pr.w;
            float dw  = pr.z * expf(l2 * 0.2f);
            float dh  = pr.w * expf(l3 * 0.2f);
            float dx0 = dcx - dw * 0.5f, dy0 = dcy - dh * 0.5f;
            float ex = (g.x - dx0) * IMG_SIZE, ey = (g.y - dy0) * IMG_SIZE;
            atomicAdd(&g_f[2], sqrtf(ex * ex + ey * ey));
            atomicAdd(&g_f[3], fabsf(g.z - (dx0 + dw)));
            atomicAdd(&g_f[4], fabsf(g.w - (dy0 + dh)));
        }
    }
    __syncthreads();
    int v = sh[threadIdx.x];
    if (v) atomicAdd(&g_hist[b][threadIdx.x], v);
}

// ---------------- K2: selection sweep + fused per-row refine + fused finalize ----
__global__ void __launch_bounds__(256) k_pass2(
        const float2* __restrict__ conf,
        const float4* __restrict__ gt4,
        const float4* __restrict__ anch,
        float* __restrict__ out, int out_size,
        int A, int B) {
    int b = blockIdx.y;
    int t = threadIdx.x;
    int base = blockIdx.x * CHUNK;
    __shared__ int sh[256];
    __shared__ float s_sum;
    __shared__ int s_corr;
    __shared__ int s_last, s_fin;

    int k = row_k(b, A);
    sh[t] = g_hist[b][t];
    if (t == 0) { s_sum = 0.0f; s_corr = 0; }
    __syncthreads();
    int c1, kk1;
    suffix_cutoff(sh, k, &c1, &kk1);
    unsigned cbin = (unsigned)c1;

    float4 g = gt4[b];
    float areaA = (g.z - g.x) * (g.w - g.y);
    size_t rowoff = (size_t)b * A;

    float lsum = 0.0f; int lcorr = 0;
    #pragma unroll 4
    for (int it = 0; it < CHUNK / 256; ++it) {
        int a = base + it * 256 + t;
        float4 pr = anch[a];
        float2 c = conf[rowoff + a];
        float d = c.y - c.x;
        bool pos;
        unsigned key = make_key(g, areaA, pr, d, &pos);
        unsigned bin = key >> 24;

        if (bin > cbin) {
            lsum += softplus(d);
            if (d <= 0.0f) lcorr++;
        }
        bool isCand = (bin == cbin);
        unsigned m = __ballot_sync(0xffffffffu, isCand);
        if (m) {
            int lane = t & 31;
            int basep = 0;
            if (lane == (__ffs(m) - 1))
                basep = atomicAdd(&g_ncand[b], __popc(m));
            basep = __shfl_sync(0xffffffffu, basep, __ffs(m) - 1);
            if (isCand) {
                int p = basep + __popc(m & ((1u << lane) - 1));
                if (p < CAP) g_cand[b][p] = key;
                atomicAdd(&g_hist2[b][(key >> 16) & 0xFFu], 1);
            }
        }
    }
    #pragma unroll
    for (int o = 16; o > 0; o >>= 1) {
        lsum  += __shfl_down_sync(0xffffffffu, lsum, o);
        lcorr += __shfl_down_sync(0xffffffffu, lcorr, o);
    }
    if ((t & 31) == 0) { atomicAdd(&s_sum, lsum); atomicAdd(&s_corr, lcorr); }
    __syncthreads();
    if (t == 0) {
        if (s_sum != 0.0f) atomicAdd(&g_f[5], s_sum);
        if (s_corr)        atomicAdd(&g_i[3], s_corr);
        __threadfence();                              // release row contributions
        int tk = atomicAdd(&g_rowticket[b], 1);
        s_last = (tk == (int)gridDim.x - 1);
    }
    __syncthreads();
    if (!s_last) return;

    // ======== last block of row b: refine within boundary bin ========
    __threadfence();                                  // acquire peers' writes

    // level 2: byte 2
    sh[t] = __ldcg(&g_hist2[b][t]);
    __syncthreads();
    int c2, kk2;
    suffix_cutoff(sh, kk1, &c2, &kk2);

    int n = __ldcg(&g_ncand[b]); if (n > CAP) n = CAP;

    // level 3: byte 1 among cand with byte2 == c2
    sh[t] = 0;
    __syncthreads();
    for (int i = t; i < n; i += 256) {
        unsigned u = __ldcg(&g_cand[b][i]);
        if (((u >> 16) & 0xFFu) == (unsigned)c2)
            atomicAdd(&sh[(u >> 8) & 0xFFu], 1);
    }
    __syncthreads();
    int c3, kk3;
    suffix_cutoff(sh, kk2, &c3, &kk3);

    // level 4: byte 0
    sh[t] = 0;
    __syncthreads();
    for (int i = t; i < n; i += 256) {
        unsigned u = __ldcg(&g_cand[b][i]);
        if (((u >> 16) & 0xFFu) == (unsigned)c2 && ((u >> 8) & 0xFFu) == (unsigned)c3)
            atomicAdd(&sh[u & 0xFFu], 1);
    }
    __syncthreads();
    int c4, kkf;
    suffix_cutoff(sh, kk3, &c4, &kkf);

    unsigned v = ((unsigned)c1 << 24) | ((unsigned)c2 << 16) |
                 ((unsigned)c3 << 8)  | (unsigned)c4;

    float rsum = 0.0f; int rcorr = 0;
    for (int i = t; i < n; i += 256) {
        unsigned u = __ldcg(&g_cand[b][i]);
        if (u > v) {
            float d = ord2f(u);
            rsum += softplus(d);
            if (d <= 0.0f) rcorr++;
        }
    }
    #pragma unroll
    for (int o = 16; o > 0; o >>= 1) {
        rsum  += __shfl_down_sync(0xffffffffu, rsum, o);
        rcorr += __shfl_down_sync(0xffffffffu, rcorr, o);
    }
    if (t == 0) { s_sum = 0.0f; s_corr = 0; }
    __syncthreads();
    if ((t & 31) == 0) { atomicAdd(&s_sum, rsum); atomicAdd(&s_corr, rcorr); }
    __syncthreads();
    if (t == 0) {
        float dv = ord2f(v);
        float tie_nll = (kkf > 0) ? (float)kkf * softplus(dv) : 0.0f;
        int   tie_cor = (kkf > 0 && dv <= 0.0f) ? kkf : 0;
        atomicAdd(&g_f[5], s_sum + tie_nll);
        atomicAdd(&g_i[3], s_corr + tie_cor);
        atomicAdd(&g_i[2], k);
        __threadfence();                              // release row results
        int r = atomicAdd(&g_rowdone, 1);
        s_fin = (r == B - 1);
    }
    __syncthreads();
    if (!s_fin) return;

    // ======== globally last block: finalize outputs + reset scratch ========
    __threadfence();                                  // acquire all rows' results
    if (t == 0) {
        float Nf0 = (float)__ldcg(&g_i[0]);
        float Nf = fmaxf(Nf0, 1.0f);
        float loss_loc = __ldcg(&g_f[0]) / (Nf * 4.0f);
        float wsum = Nf0 + (float)__ldcg(&g_i[2]) * (1.0f / 3.0f);
        float loss_cls = (__ldcg(&g_f[1]) + __ldcg(&g_f[5]) * (1.0f / 3.0f)) / wsum;
        float pos_acc = (float)__ldcg(&g_i[1]) / fmaxf((float)__ldcg(&g_i[0]), 1.0f);
        float neg_acc = (float)__ldcg(&g_i[3]) / fmaxf((float)__ldcg(&g_i[2]), 1.0f);
        float vals[8] = {loss_loc, loss_cls, pos_acc, neg_acc,
                         __ldcg(&g_f[2]) / Nf,
                         __ldcg(&g_f[3]) / Nf * IMG_SIZE,
                         __ldcg(&g_f[4]) / Nf * IMG_SIZE, Nf0};
        for (int i = 0; i < 8 && i < out_size; i++) out[i] = vals[i];
    }
    // reset scratch for the next graph replay (g_cand is overwritten, skip it)
    for (int i = t; i < MAXB * 256; i += 256) {
        ((int*)g_hist)[i] = 0;
        ((int*)g_hist2)[i] = 0;
    }
    if (t < MAXB) { g_rowpos[t] = 0; g_ncand[t] = 0; g_rowticket[t] = 0; }
    if (t < 8) g_f[t] = 0.0f;
    if (t < 4) g_i[t] = 0;
    if (t == 0) g_rowdone = 0;
}

// ---------------- launch ----------------
extern "C" void kernel_launch(void* const* d_in, const int* in_sizes, int n_in,
                              void* d_out, int out_size) {
    const float*  loc     = (const float*)d_in[0];
    const float2* conf    = (const float2*)d_in[1];
    const float4* gt      = (const float4*)d_in[2];
    const float4* anchors = (const float4*)d_in[3];
    int B = in_sizes[2] / 4;
    int A = in_sizes[3] / 4;
    if (B > MAXB) B = MAXB;
    if (A > MAXA) A = MAXA;

    int bpr = (A + CHUNK - 1) / CHUNK;
    k_pass1<<<dim3(bpr, B), 256>>>(loc, conf, gt, anchors, A);
    k_pass2<<<dim3(bpr, B), 256>>>(conf, gt, anchors, (float*)d_out, out_size, A, B);
}

// round 6
// speedup vs baseline: 1.3310x; 1.3310x over previous
#include <cuda_runtime.h>
#include <math.h>
#include <stdint.h>

#define IMG_SIZE 255.0f
#define MAXB 64
#define MAXA 65536
#define CAP   65536
#define CHUNK 4096

// ---------------- device scratch (zeroed at load; last block re-zeroes) ----------
__device__ unsigned g_key[(size_t)MAXB * MAXA];   // 16 MB: orderable keys
__device__ unsigned g_cand[MAXB][CAP];            // 16 MB: boundary-bin keys
__device__ int      g_hist[MAXB][256];
__device__ int      g_rowpos[MAXB];
__device__ int      g_ticket[MAXB];
__device__ int      g_rowdone;
// floats: 0 loss_loc_sum, 1 pos_nll_sum, 2 pos_err_sum, 3 size_x, 4 size_y, 5 neg_nll_sel
__device__ float    g_f[8];
// ints:   0 N, 1 pos_correct, 2 neg_selected_total, 3 neg_correct
__device__ int      g_i[4];

__device__ __forceinline__ float smooth_l1(float x) {
    float ax = fabsf(x);
    return (ax < 1.0f) ? 0.5f * x * x : ax - 0.5f;
}
__device__ __forceinline__ float softplus(float d) {   // nll at target 0
    return fmaxf(d, 0.0f) + log1pf(expf(-fabsf(d)));
}
__device__ __forceinline__ unsigned f2ord(float f) {
    unsigned u = __float_as_uint(f);
    return (u & 0x80000000u) ? ~u : (u | 0x80000000u);
}
__device__ __forceinline__ float ord2f(unsigned k) {
    unsigned u = (k & 0x80000000u) ? (k & 0x7FFFFFFFu) : ~k;
    return __uint_as_float(u);
}

// orderable key (0 unless label==0); IEEE division keeps labels bit-identical to ref
__device__ __forceinline__ unsigned make_key(float4 g, float areaA, float4 pr,
                                             float d, bool* pos) {
    float ax0 = pr.x - pr.z * 0.5f, ay0 = pr.y - pr.w * 0.5f;
    float ax1 = pr.x + pr.z * 0.5f, ay1 = pr.y + pr.w * 0.5f;
    float iw = fmaxf(fminf(g.z, ax1) - fmaxf(g.x, ax0), 0.0f);
    float ih = fmaxf(fminf(g.w, ay1) - fmaxf(g.y, ay0), 0.0f);
    float inter = iw * ih;
    float iou = inter / (areaA + (ax1 - ax0) * (ay1 - ay0) - inter);
    *pos = (iou >= 0.6f);
    return (iou <= 0.3f) ? f2ord(d) : 0u;
}

__device__ __noinline__ void pos_work(const float* __restrict__ loc,
                                      float4 g, float4 pr, float d,
                                      size_t idx, int b) {
    atomicAdd(&g_rowpos[b], 1);
    atomicAdd(&g_i[0], 1);
    atomicAdd(&g_f[1], softplus(-d));                 // nll at target 1
    if (d > 0.0f) atomicAdd(&g_i[1], 1);
    const float* lp = loc + idx * 4;
    float l0 = lp[0], l1 = lp[1], l2 = lp[2], l3 = lp[3];
    float gw = g.z - g.x, gh = g.w - g.y;
    float gcx = (g.x + g.z) * 0.5f, gcy = (g.y + g.w) * 0.5f;
    float e0 = (gcx - pr.x) / (0.1f * pr.z);
    float e1 = (gcy - pr.y) / (0.1f * pr.w);
    float e2 = logf(gw / pr.z) / 0.2f;
    float e3 = logf(gh / pr.w) / 0.2f;
    atomicAdd(&g_f[0], smooth_l1(l0 - e0) + smooth_l1(l1 - e1) +
                       smooth_l1(l2 - e2) + smooth_l1(l3 - e3));
    float dcx = pr.x + l0 * 0.1f * pr.z;
    float dcy = pr.y + l1 * 0.1f * pr.w;
    float dw  = pr.z * expf(l2 * 0.2f);
    float dh  = pr.w * expf(l3 * 0.2f);
    float dx0 = dcx - dw * 0.5f, dy0 = dcy - dh * 0.5f;
    float ex = (g.x - dx0) * IMG_SIZE, ey = (g.y - dy0) * IMG_SIZE;
    atomicAdd(&g_f[2], sqrtf(ex * ex + ey * ey));
    atomicAdd(&g_f[3], fabsf(g.z - (dx0 + dw)));
    atomicAdd(&g_f[4], fabsf(g.w - (dy0 + dh)));
}

// parallel cutoff over 256-bin histogram in shared s (destroyed); blockDim=256
__device__ __forceinline__ void suffix_cutoff(int* s, int k, int* out_c, int* out_kk) {
    int t = threadIdx.x;
    #pragma unroll
    for (int off = 1; off < 256; off <<= 1) {
        int add = (t + off < 256) ? s[t + off] : 0;
        __syncthreads();
        s[t] += add;
        __syncthreads();
    }
    __shared__ int sc, skk;
    if (t == 0) { sc = 0; skk = k; }
    __syncthreads();
    int St = s[t];
    int Sn = (t < 255) ? s[t + 1] : 0;
    if (Sn < k && k <= St) { sc = t; skk = k - Sn; }
    __syncthreads();
    *out_c = sc; *out_kk = skk;
}

// ---------------- the one kernel ----------------
__global__ void __launch_bounds__(256) k_fused(
        const float*  __restrict__ loc,
        const float4* __restrict__ conf4,   // conf viewed as pairs of float2
        const float4* __restrict__ gt4,
        const float4* __restrict__ anch,
        float* __restrict__ out, int out_size,
        int A, int B) {
    int b = blockIdx.y;
    int t = threadIdx.x;
    size_t rowoff = (size_t)b * A;
    __shared__ unsigned sk[CHUNK];          // 16 KB staged keys
    __shared__ int sh[256];
    __shared__ int s_last, s_fin, s_n;
    __shared__ float s_sum;
    __shared__ int s_corr;

    float4 g = gt4[b];
    float areaA = (g.z - g.x) * (g.w - g.y);
    int base = blockIdx.x * CHUNK;

    // ---- Phase A: compute keys once (conf read once), stage + store ----
    #pragma unroll 4
    for (int it = 0; it < CHUNK / 512; ++it) {        // 8 iters, 2 elems/thread
        int i2 = it * 256 + t;                        // pair index in chunk
        int a0 = base + i2 * 2;
        float4 c2 = conf4[(rowoff + (size_t)a0) >> 1];
        float4 p0 = anch[a0];
        float4 p1 = anch[a0 + 1];
        float d0 = c2.y - c2.x, d1 = c2.w - c2.z;
        bool pos0, pos1;
        unsigned k0 = make_key(g, areaA, p0, d0, &pos0);
        unsigned k1 = make_key(g, areaA, p1, d1, &pos1);
        sk[i2 * 2] = k0; sk[i2 * 2 + 1] = k1;
        reinterpret_cast<uint2*>(g_key + rowoff)[(size_t)a0 >> 1] = make_uint2(k0, k1);
        if (pos0) pos_work(loc, g, p0, d0, rowoff + a0, b);
        if (pos1) pos_work(loc, g, p1, d1, rowoff + a0 + 1, b);
    }
    sh[t] = 0;
    __syncthreads();
    // histogram from shared-staged keys (decoupled from the load pipeline)
    #pragma unroll 4
    for (int it = 0; it < CHUNK / 256; ++it) {
        unsigned bin = sk[it * 256 + t] >> 24;
        unsigned m = __match_any_sync(0xffffffffu, bin);
        if ((t & 31) == (unsigned)(__ffs(m) - 1)) atomicAdd(&sh[bin], __popc(m));
    }
    __syncthreads();
    if (sh[t]) atomicAdd(&g_hist[b][t], sh[t]);
    __threadfence();                                   // release keys+hist+pos
    if (t == 0) s_last = (atomicAdd(&g_ticket[b], 1) == (int)gridDim.x - 1);
    __syncthreads();
    if (!s_last) return;

    // ---- Phase B: last block of row b does the whole selection ----
    __threadfence();                                   // acquire peers' writes
    int np = __ldcg(&g_rowpos[b]);
    int k = 3 * np; if (k < 10) k = 10; if (k > A - 1) k = A - 1;
    sh[t] = __ldcg(&g_hist[b][t]);
    if (t == 0) { s_n = 0; s_sum = 0.0f; s_corr = 0; }
    __syncthreads();
    int c1, kk1;
    suffix_cutoff(sh, k, &c1, &kk1);
    unsigned c1u = (unsigned)c1;

    // single uint4 scan of the row's keys (256 KB, L2)
    const uint4* kp = reinterpret_cast<const uint4*>(g_key + rowoff);
    float lsum = 0.0f; int lcorr = 0;
    int n4 = A >> 2;
    for (int i = t; i < n4; i += 256) {
        uint4 u4 = __ldcg(&kp[i]);
        unsigned uu[4] = {u4.x, u4.y, u4.z, u4.w};
        #pragma unroll
        for (int j = 0; j < 4; ++j) {
            unsigned u = uu[j];
            unsigned bin = u >> 24;
            if (bin > c1u) {
                float d = ord2f(u);
                lsum += softplus(d);
                if (u <= 0x80000000u) lcorr++;         // d <= 0 -> pred==0
            } else if (bin == c1u) {
                int p = atomicAdd(&s_n, 1);
                if (p < CAP) g_cand[b][p] = u;
            }
        }
    }
    #pragma unroll
    for (int o = 16; o > 0; o >>= 1) {
        lsum  += __shfl_down_sync(0xffffffffu, lsum, o);
        lcorr += __shfl_down_sync(0xffffffffu, lcorr, o);
    }
    if ((t & 31) == 0) { atomicAdd(&s_sum, lsum); atomicAdd(&s_corr, lcorr); }
    __syncthreads();
    int n = s_n; if (n > CAP) n = CAP;

    // drill bytes 2/1/0 within boundary bin
    sh[t] = 0;
    __syncthreads();
    for (int i = t; i < n; i += 256)
        atomicAdd(&sh[(__ldcg(&g_cand[b][i]) >> 16) & 0xFFu], 1);
    __syncthreads();
    int c2, kk2;
    suffix_cutoff(sh, kk1, &c2, &kk2);

    sh[t] = 0;
    __syncthreads();
    for (int i = t; i < n; i += 256) {
        unsigned u = __ldcg(&g_cand[b][i]);
        if (((u >> 16) & 0xFFu) == (unsigned)c2) atomicAdd(&sh[(u >> 8) & 0xFFu], 1);
    }
    __syncthreads();
    int c3, kk3;
    suffix_cutoff(sh, kk2, &c3, &kk3);

    sh[t] = 0;
    __syncthreads();
    for (int i = t; i < n; i += 256) {
        unsigned u = __ldcg(&g_cand[b][i]);
        if (((u >> 16) & 0xFFu) == (unsigned)c2 && ((u >> 8) & 0xFFu) == (unsigned)c3)
            atomicAdd(&sh[u & 0xFFu], 1);
    }
    __syncthreads();
    int c4, kkf;
    suffix_cutoff(sh, kk3, &c4, &kkf);

    unsigned v = (c1u << 24) | ((unsigned)c2 << 16) | ((unsigned)c3 << 8) | (unsigned)c4;

    float rsum = 0.0f; int rcorr = 0;
    for (int i = t; i < n; i += 256) {
        unsigned u = __ldcg(&g_cand[b][i]);
        if (u > v) {
            rsum += softplus(ord2f(u));
            if (u <= 0x80000000u) rcorr++;
        }
    }
    #pragma unroll
    for (int o = 16; o > 0; o >>= 1) {
        rsum  += __shfl_down_sync(0xffffffffu, rsum, o);
        rcorr += __shfl_down_sync(0xffffffffu, rcorr, o);
    }
    if ((t & 31) == 0) { atomicAdd(&s_sum, rsum); atomicAdd(&s_corr, rcorr); }
    __syncthreads();
    if (t == 0) {
        float dv = ord2f(v);
        float tie_nll = (kkf > 0) ? (float)kkf * softplus(dv) : 0.0f;
        int   tie_cor = (kkf > 0 && v <= 0x80000000u) ? kkf : 0;
        atomicAdd(&g_f[5], s_sum + tie_nll);
        atomicAdd(&g_i[3], s_corr + tie_cor);
        atomicAdd(&g_i[2], k);
        __threadfence();
        s_fin = (atomicAdd(&g_rowdone, 1) == B - 1);
    }
    __syncthreads();
    if (!s_fin) return;

    // ---- Phase C: globally last block finalizes + resets scratch ----
    __threadfence();
    if (t == 0) {
        float Nf0 = (float)__ldcg(&g_i[0]);
        float Nf = fmaxf(Nf0, 1.0f);
        float loss_loc = __ldcg(&g_f[0]) / (Nf * 4.0f);
        float wsum = Nf0 + (float)__ldcg(&g_i[2]) * (1.0f / 3.0f);
        float loss_cls = (__ldcg(&g_f[1]) + __ldcg(&g_f[5]) * (1.0f / 3.0f)) / wsum;
        float pos_acc = (float)__ldcg(&g_i[1]) / fmaxf((float)__ldcg(&g_i[0]), 1.0f);
        float neg_acc = (float)__ldcg(&g_i[3]) / fmaxf((float)__ldcg(&g_i[2]), 1.0f);
        float vals[8] = {loss_loc, loss_cls, pos_acc, neg_acc,
                         __ldcg(&g_f[2]) / Nf,
                         __ldcg(&g_f[3]) / Nf * IMG_SIZE,
                         __ldcg(&g_f[4]) / Nf * IMG_SIZE, Nf0};
        for (int i = 0; i < 8 && i < out_size; i++) out[i] = vals[i];
    }
    for (int i = t; i < MAXB * 256; i += 256) ((int*)g_hist)[i] = 0;
    if (t < MAXB) { g_rowpos[t] = 0; g_ticket[t] = 0; }
    if (t < 8) g_f[t] = 0.0f;
    if (t < 4) g_i[t] = 0;
    if (t == 0) g_rowdone = 0;
}

// ---------------- launch ----------------
extern "C" void kernel_launch(void* const* d_in, const int* in_sizes, int n_in,
                              void* d_out, int out_size) {
    const float*  loc     = (const float*)d_in[0];
    const float4* conf4   = (const float4*)d_in[1];
    const float4* gt      = (const float4*)d_in[2];
    const float4* anchors = (const float4*)d_in[3];
    int B = in_sizes[2] / 4;
    int A = in_sizes[3] / 4;
    if (B > MAXB) B = MAXB;
    if (A > MAXA) A = MAXA;

    int bpr = (A + CHUNK - 1) / CHUNK;   // 16 for A=65536
    k_fused<<<dim3(bpr, B), 256>>>(loc, conf4, gt, anchors,
                                   (float*)d_out, out_size, A, B);
}